// round 3
// baseline (speedup 1.0000x reference)
#include <cuda_runtime.h>
#include <math.h>

#define BSN   100
#define CCH   640
#define W_IN  19
#define IMG   (W_IN * W_IN)           // 361
#define NW    5
#define P25   25
#define META_PER_BS (2 * CCH * P25)   // 32000
#define META_TOTAL  (BSN * META_PER_BS)

// ---------------------------------------------------------------------------
// Kernel 1: adaptive avg pool 19x19 -> 5x5.
// 32 images/block, 128 threads, 4000 blocks (4 blocks/SM for overlap).
// Compute: 4 threads per image (rows split mod 4), xor-shuffle reduce.
// ---------------------------------------------------------------------------
#define IMGS_PB 32
#define POOL_SMEM_FLOATS (IMGS_PB * IMG)   // 11552
#define POOL_THREADS 128

__global__ __launch_bounds__(POOL_THREADS, 4) void pool_kernel(
    const float* __restrict__ s_in,
    const float* __restrict__ q_in,
    float* __restrict__ out)
{
    extern __shared__ float smem[];            // 11552 floats
    __shared__ float osm[IMGS_PB * P25];       // 800 floats

    const int blk = blockIdx.x;                // 0..3999
    const int tid = threadIdx.x;
    const int sel = (blk >= 2000) ? 1 : 0;
    const int lblk = blk - sel * 2000;         // 0..1999

    // ---- coalesced staged load: 11552 floats = 2888 float4 ----
    const float4* __restrict__ src4 = (const float4*)(
        (sel ? q_in : s_in) + (size_t)lblk * POOL_SMEM_FLOATS);
    float4* __restrict__ smem4 = (float4*)smem;
    for (int i = tid; i < POOL_SMEM_FLOATS / 4; i += POOL_THREADS)
        smem4[i] = src4[i];
    __syncthreads();

    // ---- compute: 4 threads per image ----
    {
        const int m = tid >> 2;        // image 0..31
        const int t = tid & 3;         // row-phase
        const float* __restrict__ img = smem + m * IMG;

        const int BSTART[NW] = {0, 3, 7, 11, 15};
        const int BEND[NW]   = {4, 8, 12, 16, 19};
        const float INVLEN[NW] = {0.25f, 0.2f, 0.2f, 0.2f, 0.25f};

        float acc[NW][NW];
#pragma unroll
        for (int i = 0; i < NW; i++)
#pragma unroll
            for (int j = 0; j < NW; j++) acc[i][j] = 0.0f;

#pragma unroll
        for (int r = 0; r < W_IN; r++) {
            if ((r & 3) == t) {
                float row[W_IN];
#pragma unroll
                for (int w = 0; w < W_IN; w++)
                    row[w] = img[r * W_IN + w];
                float cs[NW];
#pragma unroll
                for (int j = 0; j < NW; j++) {
                    float v = 0.0f;
#pragma unroll
                    for (int w = BSTART[j]; w < BEND[j]; w++) v += row[w];
                    cs[j] = v;
                }
#pragma unroll
                for (int i = 0; i < NW; i++) {
                    if (r >= BSTART[i] && r < BEND[i]) {
#pragma unroll
                        for (int j = 0; j < NW; j++) acc[i][j] += cs[j];
                    }
                }
            }
        }

        // reduce across the 4 threads of this image (lanes m*4+t, aligned)
#pragma unroll
        for (int i = 0; i < NW; i++)
#pragma unroll
            for (int j = 0; j < NW; j++) {
                acc[i][j] += __shfl_xor_sync(0xffffffffu, acc[i][j], 1);
                acc[i][j] += __shfl_xor_sync(0xffffffffu, acc[i][j], 2);
            }

        // all 4 lanes hold totals; spread the 25 stores across them
#pragma unroll
        for (int idx = 0; idx < P25; idx++) {
            const int i = idx / NW, j = idx % NW;
            if ((idx & 3) == t)
                osm[m * P25 + idx] = acc[i][j] * INVLEN[i] * INVLEN[j];
        }
    }
    __syncthreads();

    // ---- coalesced store: 32 images -> 800 consecutive floats ----
    const int img0 = lblk * IMGS_PB;
    const int bs = img0 / CCH;
    const int c0 = img0 - bs * CCH;
    float* __restrict__ dst =
        out + (size_t)bs * META_PER_BS + (size_t)(sel * CCH + c0) * P25;
    for (int i = tid; i < IMGS_PB * P25; i += POOL_THREADS)
        dst[i] = osm[i];
}

// ---------------------------------------------------------------------------
// Kernel 2: all-pairs cosine similarity + max over query positions.
// 800 threads = 25 warps; warp w owns 5x5 (p,q) tile; float4 LDS dot loop.
// smem rows [p][c] stride 648 (16B aligned, conflict-free full-width LDS.128).
// ---------------------------------------------------------------------------
#define CST 648
#define COS_THREADS 800
#define COS_SMEM_FLOATS (2 * P25 * CST)   // 32400

__global__ __launch_bounds__(COS_THREADS) void cosine_kernel(
    const float* __restrict__ meta,
    float* __restrict__ out)
{
    extern __shared__ float sm[];
    float* __restrict__ sf = sm;              // [25][648]
    float* __restrict__ qf = sm + P25 * CST;  // [25][648]
    __shared__ float sn[P25];
    __shared__ float qn[P25];
    __shared__ float simbuf[P25 * P25];

    const int bs  = blockIdx.x;
    const int tid = threadIdx.x;
    const float4* __restrict__ base4 =
        (const float4*)(meta + (size_t)bs * META_PER_BS);

    // stage with transpose, float4 global loads (32000 = 8000 float4)
    for (int i4 = tid; i4 < META_PER_BS / 4; i4 += COS_THREADS) {
        float4 v = base4[i4];
        int i = i4 << 2;
        int ch = i / P25;
        int p  = i - ch * P25;
        float vals[4] = {v.x, v.y, v.z, v.w};
#pragma unroll
        for (int e = 0; e < 4; e++) {
            float* dstp = (ch >= CCH) ? qf : sf;
            int c = (ch >= CCH) ? (ch - CCH) : ch;
            dstp[p * CST + c] = vals[e];
            if (++p == P25) { p = 0; ch++; }
        }
    }
    __syncthreads();

    // ---- norms: 50 norms x 16 threads, float4 ----
    {
        const int nid = tid >> 4;          // 0..49
        const int sub = tid & 15;
        const int p = (nid >= P25) ? (nid - P25) : nid;
        const float* __restrict__ f = ((nid >= P25) ? qf : sf) + p * CST;
        float v = 0.0f;
#pragma unroll
        for (int c4 = sub; c4 < CCH / 4; c4 += 16) {
            float4 x = ((const float4*)f)[c4];
            v += x.x * x.x + x.y * x.y + x.z * x.z + x.w * x.w;
        }
#pragma unroll
        for (int off = 8; off; off >>= 1)
            v += __shfl_xor_sync(0xffffffffu, v, off);
        if (sub == 0) {
            if (nid >= P25) qn[p] = sqrtf(v);
            else            sn[p] = sqrtf(v);
        }
    }

    // ---- dots: warp w = (pg,qg) 5x5 tile, float4 lane-parallel c ----
    {
        const int w = tid >> 5;            // 0..24
        const int lane = tid & 31;
        const int pg = (w / NW) * NW;
        const int qg = (w % NW) * NW;

        float acc[NW][NW];
#pragma unroll
        for (int i = 0; i < NW; i++)
#pragma unroll
            for (int j = 0; j < NW; j++) acc[i][j] = 0.0f;

#pragma unroll
        for (int k = 0; k < CCH / 128; k++) {   // 5 iters, 128 c each
            const int c = k * 128 + lane * 4;
            float4 sv[NW], qv[NW];
#pragma unroll
            for (int i = 0; i < NW; i++)
                sv[i] = *(const float4*)&sf[(pg + i) * CST + c];
#pragma unroll
            for (int j = 0; j < NW; j++)
                qv[j] = *(const float4*)&qf[(qg + j) * CST + c];
#pragma unroll
            for (int i = 0; i < NW; i++)
#pragma unroll
                for (int j = 0; j < NW; j++) {
                    float a = acc[i][j];
                    a = fmaf(sv[i].x, qv[j].x, a);
                    a = fmaf(sv[i].y, qv[j].y, a);
                    a = fmaf(sv[i].z, qv[j].z, a);
                    a = fmaf(sv[i].w, qv[j].w, a);
                    acc[i][j] = a;
                }
        }
        // reduce 25 accumulators across lanes
#pragma unroll
        for (int off = 16; off; off >>= 1)
#pragma unroll
            for (int i = 0; i < NW; i++)
#pragma unroll
                for (int j = 0; j < NW; j++)
                    acc[i][j] += __shfl_down_sync(0xffffffffu, acc[i][j], off);

        if (lane == 0) {
#pragma unroll
            for (int i = 0; i < NW; i++)
#pragma unroll
                for (int j = 0; j < NW; j++)
                    simbuf[(pg + i) * P25 + (qg + j)] = acc[i][j];
        }
    }
    __syncthreads();

    // ---- divide by norms + max over q ----
    if (tid < P25) {
        const float snp = sn[tid];
        float m = -INFINITY;
#pragma unroll
        for (int q = 0; q < P25; q++) {
            float den = fmaxf(snp * qn[q], 1e-8f);
            m = fmaxf(m, simbuf[tid * P25 + q] / den);
        }
        out[bs * P25 + tid] = m;
    }
}

extern "C" void kernel_launch(void* const* d_in, const int* in_sizes, int n_in,
                              void* d_out, int out_size)
{
    const float* s_in = (const float*)d_in[0];
    const float* q_in = (const float*)d_in[1];
    float* out = (float*)d_out;

    static bool attr_set = false;
    if (!attr_set) {
        cudaFuncSetAttribute(pool_kernel,
                             cudaFuncAttributeMaxDynamicSharedMemorySize,
                             POOL_SMEM_FLOATS * (int)sizeof(float));
        cudaFuncSetAttribute(cosine_kernel,
                             cudaFuncAttributeMaxDynamicSharedMemorySize,
                             COS_SMEM_FLOATS * (int)sizeof(float));
        attr_set = true;
    }

    pool_kernel<<<4000, POOL_THREADS, POOL_SMEM_FLOATS * sizeof(float)>>>(
        s_in, q_in, out);
    cosine_kernel<<<BSN, COS_THREADS, COS_SMEM_FLOATS * sizeof(float)>>>(
        out, out + META_TOTAL);
}

// round 4
// speedup vs baseline: 1.1897x; 1.1897x over previous
#include <cuda_runtime.h>
#include <math.h>

#define BSN   100
#define CCH   640
#define W_IN  19
#define IMG   (W_IN * W_IN)           // 361
#define NW    5
#define P25   25
#define META_PER_BS (2 * CCH * P25)   // 32000
#define META_TOTAL  (BSN * META_PER_BS)

// ---------------------------------------------------------------------------
// Kernel 1: adaptive avg pool 19x19 -> 5x5.
// 64 images/block, 256 threads, 2000 blocks (2 blocks/SM, 92.4 KB smem).
// Load: 22 front-batched float4 LDGs per thread (MLP ~22) + remainder.
// Compute: 2 threads/image, compile-time row ranges (no predication),
// one xor-shuffle combine. Store coalesced.
// ---------------------------------------------------------------------------
#define IMGS_PB 64
#define POOL_SMEM_FLOATS (IMGS_PB * IMG)   // 23104
#define POOL_N4 (POOL_SMEM_FLOATS / 4)     // 5776
#define POOL_THREADS 256
#define POOL_FULL_ITERS 22                 // 22*256 = 5632; remainder 144

__device__ __forceinline__ void pool_cols(const float* __restrict__ row_base,
                                          float cs[NW])
{
    const int BSTART[NW] = {0, 3, 7, 11, 15};
    const int BEND[NW]   = {4, 8, 12, 16, 19};
    float row[W_IN];
#pragma unroll
    for (int w = 0; w < W_IN; w++) row[w] = row_base[w];
#pragma unroll
    for (int j = 0; j < NW; j++) {
        float v = 0.0f;
#pragma unroll
        for (int w = BSTART[j]; w < BEND[j]; w++) v += row[w];
        cs[j] = v;
    }
}

template<int R0, int R1>
__device__ __forceinline__ void pool_rows(const float* __restrict__ img,
                                          float acc[NW][NW])
{
    const int BSTART[NW] = {0, 3, 7, 11, 15};
    const int BEND[NW]   = {4, 8, 12, 16, 19};
#pragma unroll
    for (int r = R0; r < R1; r++) {
        float cs[NW];
        pool_cols(img + r * W_IN, cs);
#pragma unroll
        for (int i = 0; i < NW; i++) {
            if (r >= BSTART[i] && r < BEND[i]) {   // compile-time resolved
#pragma unroll
                for (int j = 0; j < NW; j++) acc[i][j] += cs[j];
            }
        }
    }
}

__global__ __launch_bounds__(POOL_THREADS) void pool_kernel(
    const float* __restrict__ s_in,
    const float* __restrict__ q_in,
    float* __restrict__ out)
{
    extern __shared__ float smem[];            // 23104 floats
    __shared__ float osm[IMGS_PB * P25];       // 1600 floats

    const int blk = blockIdx.x;                // 0..1999
    const int tid = threadIdx.x;
    const int sel = (blk >= 1000) ? 1 : 0;
    const int lblk = blk - sel * 1000;

    // ---- front-batched staged load: MLP ~22 per thread ----
    const float4* __restrict__ src4 = (const float4*)(
        (sel ? q_in : s_in) + (size_t)lblk * POOL_SMEM_FLOATS);
    float4* __restrict__ smem4 = (float4*)smem;
    {
        float4 v[POOL_FULL_ITERS];
#pragma unroll
        for (int k = 0; k < POOL_FULL_ITERS; k++)
            v[k] = src4[tid + k * POOL_THREADS];
        float4 vr;
        const bool has_r = (tid < POOL_N4 - POOL_FULL_ITERS * POOL_THREADS);
        if (has_r) vr = src4[POOL_FULL_ITERS * POOL_THREADS + tid];
#pragma unroll
        for (int k = 0; k < POOL_FULL_ITERS; k++)
            smem4[tid + k * POOL_THREADS] = v[k];
        if (has_r) smem4[POOL_FULL_ITERS * POOL_THREADS + tid] = vr;
    }
    __syncthreads();

    // ---- compute: 2 threads per image, straight-line halves ----
    {
        const int m = tid >> 1;        // image 0..127 (only <64 valid)
        const int t = tid & 1;
        if (m < IMGS_PB) {
            const float* __restrict__ img = smem + m * IMG;
            const float INVLEN[NW] = {0.25f, 0.2f, 0.2f, 0.2f, 0.25f};

            float acc[NW][NW];
#pragma unroll
            for (int i = 0; i < NW; i++)
#pragma unroll
                for (int j = 0; j < NW; j++) acc[i][j] = 0.0f;

            if (t == 0) pool_rows<0, 10>(img, acc);
            else        pool_rows<10, 19>(img, acc);

            // combine partner lanes (m*2 and m*2+1 are adjacent)
#pragma unroll
            for (int i = 0; i < NW; i++)
#pragma unroll
                for (int j = 0; j < NW; j++)
                    acc[i][j] += __shfl_xor_sync(0xffffffffu, acc[i][j], 1);

            // both lanes have totals; split the 25 stores by parity
#pragma unroll
            for (int idx = 0; idx < P25; idx++) {
                if ((idx & 1) == t) {
                    const int i = idx / NW, j = idx % NW;
                    osm[m * P25 + idx] = acc[i][j] * INVLEN[i] * INVLEN[j];
                }
            }
        }
    }
    __syncthreads();

    // ---- coalesced store: 64 images -> 1600 consecutive floats ----
    const int img0 = lblk * IMGS_PB;
    const int bs = img0 / CCH;
    const int c0 = img0 - bs * CCH;
    float* __restrict__ dst =
        out + (size_t)bs * META_PER_BS + (size_t)(sel * CCH + c0) * P25;
#pragma unroll
    for (int i = tid; i < IMGS_PB * P25; i += POOL_THREADS)
        dst[i] = osm[i];
}

// ---------------------------------------------------------------------------
// Kernel 2: all-pairs cosine similarity + max over query positions.
// (unchanged from R3: measured 15.9 us)
// ---------------------------------------------------------------------------
#define CST 648
#define COS_THREADS 800
#define COS_SMEM_FLOATS (2 * P25 * CST)   // 32400

__global__ __launch_bounds__(COS_THREADS) void cosine_kernel(
    const float* __restrict__ meta,
    float* __restrict__ out)
{
    extern __shared__ float sm[];
    float* __restrict__ sf = sm;              // [25][648]
    float* __restrict__ qf = sm + P25 * CST;  // [25][648]
    __shared__ float sn[P25];
    __shared__ float qn[P25];
    __shared__ float simbuf[P25 * P25];

    const int bs  = blockIdx.x;
    const int tid = threadIdx.x;
    const float4* __restrict__ base4 =
        (const float4*)(meta + (size_t)bs * META_PER_BS);

    for (int i4 = tid; i4 < META_PER_BS / 4; i4 += COS_THREADS) {
        float4 v = base4[i4];
        int i = i4 << 2;
        int ch = i / P25;
        int p  = i - ch * P25;
        float vals[4] = {v.x, v.y, v.z, v.w};
#pragma unroll
        for (int e = 0; e < 4; e++) {
            float* dstp = (ch >= CCH) ? qf : sf;
            int c = (ch >= CCH) ? (ch - CCH) : ch;
            dstp[p * CST + c] = vals[e];
            if (++p == P25) { p = 0; ch++; }
        }
    }
    __syncthreads();

    {
        const int nid = tid >> 4;          // 0..49
        const int sub = tid & 15;
        const int p = (nid >= P25) ? (nid - P25) : nid;
        const float* __restrict__ f = ((nid >= P25) ? qf : sf) + p * CST;
        float v = 0.0f;
#pragma unroll
        for (int c4 = sub; c4 < CCH / 4; c4 += 16) {
            float4 x = ((const float4*)f)[c4];
            v += x.x * x.x + x.y * x.y + x.z * x.z + x.w * x.w;
        }
#pragma unroll
        for (int off = 8; off; off >>= 1)
            v += __shfl_xor_sync(0xffffffffu, v, off);
        if (sub == 0) {
            if (nid >= P25) qn[p] = sqrtf(v);
            else            sn[p] = sqrtf(v);
        }
    }

    {
        const int w = tid >> 5;            // 0..24
        const int lane = tid & 31;
        const int pg = (w / NW) * NW;
        const int qg = (w % NW) * NW;

        float acc[NW][NW];
#pragma unroll
        for (int i = 0; i < NW; i++)
#pragma unroll
            for (int j = 0; j < NW; j++) acc[i][j] = 0.0f;

#pragma unroll
        for (int k = 0; k < CCH / 128; k++) {
            const int c = k * 128 + lane * 4;
            float4 sv[NW], qv[NW];
#pragma unroll
            for (int i = 0; i < NW; i++)
                sv[i] = *(const float4*)&sf[(pg + i) * CST + c];
#pragma unroll
            for (int j = 0; j < NW; j++)
                qv[j] = *(const float4*)&qf[(qg + j) * CST + c];
#pragma unroll
            for (int i = 0; i < NW; i++)
#pragma unroll
                for (int j = 0; j < NW; j++) {
                    float a = acc[i][j];
                    a = fmaf(sv[i].x, qv[j].x, a);
                    a = fmaf(sv[i].y, qv[j].y, a);
                    a = fmaf(sv[i].z, qv[j].z, a);
                    a = fmaf(sv[i].w, qv[j].w, a);
                    acc[i][j] = a;
                }
        }
#pragma unroll
        for (int off = 16; off; off >>= 1)
#pragma unroll
            for (int i = 0; i < NW; i++)
#pragma unroll
                for (int j = 0; j < NW; j++)
                    acc[i][j] += __shfl_down_sync(0xffffffffu, acc[i][j], off);

        if (lane == 0) {
#pragma unroll
            for (int i = 0; i < NW; i++)
#pragma unroll
                for (int j = 0; j < NW; j++)
                    simbuf[(pg + i) * P25 + (qg + j)] = acc[i][j];
        }
    }
    __syncthreads();

    if (tid < P25) {
        const float snp = sn[tid];
        float m = -INFINITY;
#pragma unroll
        for (int q = 0; q < P25; q++) {
            float den = fmaxf(snp * qn[q], 1e-8f);
            m = fmaxf(m, simbuf[tid * P25 + q] / den);
        }
        out[bs * P25 + tid] = m;
    }
}

extern "C" void kernel_launch(void* const* d_in, const int* in_sizes, int n_in,
                              void* d_out, int out_size)
{
    const float* s_in = (const float*)d_in[0];
    const float* q_in = (const float*)d_in[1];
    float* out = (float*)d_out;

    static bool attr_set = false;
    if (!attr_set) {
        cudaFuncSetAttribute(pool_kernel,
                             cudaFuncAttributeMaxDynamicSharedMemorySize,
                             POOL_SMEM_FLOATS * (int)sizeof(float));
        cudaFuncSetAttribute(cosine_kernel,
                             cudaFuncAttributeMaxDynamicSharedMemorySize,
                             COS_SMEM_FLOATS * (int)sizeof(float));
        attr_set = true;
    }

    pool_kernel<<<2000, POOL_THREADS, POOL_SMEM_FLOATS * sizeof(float)>>>(
        s_in, q_in, out);
    cosine_kernel<<<BSN, COS_THREADS, COS_SMEM_FLOATS * sizeof(float)>>>(
        out, out + META_TOTAL);
}

// round 5
// speedup vs baseline: 1.3072x; 1.0987x over previous
#include <cuda_runtime.h>
#include <math.h>

#define BSN   100
#define CCH   640
#define W_IN  19
#define IMG   (W_IN * W_IN)           // 361
#define NW    5
#define P25   25
#define META_PER_BS (2 * CCH * P25)   // 32000
#define META_TOTAL  (BSN * META_PER_BS)

// ---------------------------------------------------------------------------
// Kernel 1: adaptive avg pool 19x19 -> 5x5.
// 16 images/block, 128 threads, 8000 blocks (~7 blocks/SM => load/compute
// phases of different blocks overlap). Two-stage straight-line compute using
// ALL threads; direct coalesced global store (no osm buffer).
// ---------------------------------------------------------------------------
#define IMGS_PB 16
#define POOL_IN_FLOATS (IMGS_PB * IMG)   // 5776
#define POOL_N4 (POOL_IN_FLOATS / 4)     // 1444
#define POOL_THREADS 128
#define POOL_FULL 11                     // 11*128 = 1408, remainder 36

__global__ __launch_bounds__(POOL_THREADS, 7) void pool_kernel(
    const float* __restrict__ s_in,
    const float* __restrict__ q_in,
    float* __restrict__ out)
{
    __shared__ float sin_[POOL_IN_FLOATS];       // 23104 B
    __shared__ float sA[IMGS_PB * W_IN * NW];    // 16*19*5 = 1520 floats

    const int blk = blockIdx.x;                  // 0..7999
    const int tid = threadIdx.x;
    const int sel = (blk >= 4000) ? 1 : 0;
    const int lblk = blk - sel * 4000;           // 0..3999

    // ---- staged load: 1444 float4, 11 full rounds + 36 remainder ----
    const float4* __restrict__ src4 = (const float4*)(
        (sel ? q_in : s_in) + (size_t)lblk * POOL_IN_FLOATS);
    float4* __restrict__ s4 = (float4*)sin_;
    {
        float4 v[POOL_FULL];
#pragma unroll
        for (int k = 0; k < POOL_FULL; k++)
            v[k] = src4[tid + k * POOL_THREADS];
        float4 vr;
        const bool hr = (tid < POOL_N4 - POOL_FULL * POOL_THREADS);
        if (hr) vr = src4[POOL_FULL * POOL_THREADS + tid];
#pragma unroll
        for (int k = 0; k < POOL_FULL; k++)
            s4[tid + k * POOL_THREADS] = v[k];
        if (hr) s4[POOL_FULL * POOL_THREADS + tid] = vr;
    }
    __syncthreads();

    // ---- stage A: column-bin each row. thread = (img, row); 304 tasks ----
    // sin_[idx*19 + w] -> sA[idx*5 + j]   (stride 19 & 5: conflict-free)
#pragma unroll
    for (int base = 0; base < IMGS_PB * W_IN; base += POOL_THREADS) {
        const int idx = base + tid;
        if (idx < IMGS_PB * W_IN) {
            const float* __restrict__ row = sin_ + idx * W_IN;
            float r[W_IN];
#pragma unroll
            for (int w = 0; w < W_IN; w++) r[w] = row[w];
            const int BS_[NW] = {0, 3, 7, 11, 15};
            const int BE_[NW] = {4, 8, 12, 16, 19};
#pragma unroll
            for (int j = 0; j < NW; j++) {
                float v = 0.0f;
#pragma unroll
                for (int w = BS_[j]; w < BE_[j]; w++) v += r[w];
                sA[idx * NW + j] = v;
            }
        }
    }
    __syncthreads();

    // ---- stage B: row-bin + scale + DIRECT coalesced global store ----
    // output task idx in [0,400): img = idx/25, o = idx%25, i = o/5, j = o%5
    // dst[idx] is exactly the right meta location (images contiguous).
    const int img0 = lblk * IMGS_PB;
    const int bs = img0 / CCH;
    const int c0 = img0 - bs * CCH;
    float* __restrict__ dst =
        out + (size_t)bs * META_PER_BS + (size_t)(sel * CCH + c0) * P25;

#pragma unroll
    for (int base = 0; base < IMGS_PB * P25; base += POOL_THREADS) {
        const int idx = base + tid;
        if (idx < IMGS_PB * P25) {
            const int img = idx / P25;
            const int o = idx - img * P25;
            const int i = o / NW;
            const int j = o - i * NW;
            const int rs = (19 * i) / 5;
            const int leni = (19 * i + 23) / 5 - rs;       // 4 or 5
            const int lenj = (19 * j + 23) / 5 - (19 * j) / 5;
            const float* __restrict__ a = sA + (img * W_IN + rs) * NW + j;
            float v = a[0] + a[1 * NW] + a[2 * NW] + a[3 * NW];
            if (leni == 5) v += a[4 * NW];
            const float invi = (leni == 4) ? 0.25f : 0.2f;
            const float invj = (lenj == 4) ? 0.25f : 0.2f;
            dst[idx] = v * invi * invj;
        }
    }
}

// ---------------------------------------------------------------------------
// Kernel 2: all-pairs cosine similarity + max over query positions.
// 800 threads = 25 warps; warp w owns 5x5 (p,q) tile.
// Dot loop: float2 lanes + packed fma.rn.f32x2 (halves FMA issue count).
// Staging: exactly 10 front-batched float4 LDGs per thread.
// ---------------------------------------------------------------------------
#define CST 648
#define COS_THREADS 800
#define COS_SMEM_FLOATS (2 * P25 * CST)   // 32400

__device__ __forceinline__ void fma_x2(unsigned long long& acc,
                                       unsigned long long a,
                                       unsigned long long b)
{
    asm("fma.rn.f32x2 %0, %1, %2, %0;" : "+l"(acc) : "l"(a), "l"(b));
}

__global__ __launch_bounds__(COS_THREADS, 1) void cosine_kernel(
    const float* __restrict__ meta,
    float* __restrict__ out)
{
    extern __shared__ float sm[];
    float* __restrict__ sf = sm;              // [25][648]
    float* __restrict__ qf = sm + P25 * CST;  // [25][648]
    __shared__ float sn[P25];
    __shared__ float qn[P25];
    __shared__ float simbuf[P25 * P25];

    const int bs  = blockIdx.x;
    const int tid = threadIdx.x;
    const float4* __restrict__ base4 =
        (const float4*)(meta + (size_t)bs * META_PER_BS);

    // ---- staging: 8000 float4 / 800 threads = 10 each, front-batched ----
    {
        float4 v[10];
#pragma unroll
        for (int k = 0; k < 10; k++)
            v[k] = base4[tid + k * COS_THREADS];
#pragma unroll
        for (int k = 0; k < 10; k++) {
            int i = (tid + k * COS_THREADS) << 2;
            int ch = i / P25;
            int p  = i - ch * P25;
            float vals[4] = {v[k].x, v[k].y, v[k].z, v[k].w};
#pragma unroll
            for (int e = 0; e < 4; e++) {
                float* dstp = (ch >= CCH) ? qf : sf;
                int c = (ch >= CCH) ? (ch - CCH) : ch;
                dstp[p * CST + c] = vals[e];
                if (++p == P25) { p = 0; ch++; }
            }
        }
    }
    __syncthreads();

    // ---- norms: 50 norms x 16 threads, float4 ----
    {
        const int nid = tid >> 4;          // 0..49
        const int sub = tid & 15;
        const int p = (nid >= P25) ? (nid - P25) : nid;
        const float* __restrict__ f = ((nid >= P25) ? qf : sf) + p * CST;
        float v = 0.0f;
#pragma unroll
        for (int c4 = sub; c4 < CCH / 4; c4 += 16) {
            float4 x = ((const float4*)f)[c4];
            v += x.x * x.x + x.y * x.y + x.z * x.z + x.w * x.w;
        }
#pragma unroll
        for (int off = 8; off; off >>= 1)
            v += __shfl_xor_sync(0xffffffffu, v, off);
        if (sub == 0) {
            if (nid >= P25) qn[p] = sqrtf(v);
            else            sn[p] = sqrtf(v);
        }
    }

    // ---- dots: warp = 5x5 (p,q) tile; float2 lanes; packed f32x2 FMA ----
    {
        const int w = tid >> 5;            // 0..24
        const int lane = tid & 31;
        const int pg = (w / NW) * NW;
        const int qg = (w % NW) * NW;

        unsigned long long acc[NW][NW];
#pragma unroll
        for (int i = 0; i < NW; i++)
#pragma unroll
            for (int j = 0; j < NW; j++) acc[i][j] = 0ull;

#pragma unroll
        for (int k = 0; k < CCH / 64; k++) {   // 10 iters, 64 c each
            const int c = k * 64 + lane * 2;
            unsigned long long sv[NW];
#pragma unroll
            for (int i = 0; i < NW; i++)
                sv[i] = *(const unsigned long long*)&sf[(pg + i) * CST + c];
#pragma unroll
            for (int j = 0; j < NW; j++) {
                const unsigned long long qv =
                    *(const unsigned long long*)&qf[(qg + j) * CST + c];
#pragma unroll
                for (int i = 0; i < NW; i++)
                    fma_x2(acc[i][j], sv[i], qv);
            }
        }

        // unpack pairs -> scalar, reduce across lanes
        float accs[NW][NW];
#pragma unroll
        for (int i = 0; i < NW; i++)
#pragma unroll
            for (int j = 0; j < NW; j++) {
                unsigned int lo = (unsigned int)(acc[i][j] & 0xffffffffull);
                unsigned int hi = (unsigned int)(acc[i][j] >> 32);
                accs[i][j] = __uint_as_float(lo) + __uint_as_float(hi);
            }
#pragma unroll
        for (int off = 16; off; off >>= 1)
#pragma unroll
            for (int i = 0; i < NW; i++)
#pragma unroll
                for (int j = 0; j < NW; j++)
                    accs[i][j] += __shfl_down_sync(0xffffffffu, accs[i][j], off);

        if (lane == 0) {
#pragma unroll
            for (int i = 0; i < NW; i++)
#pragma unroll
                for (int j = 0; j < NW; j++)
                    simbuf[(pg + i) * P25 + (qg + j)] = accs[i][j];
        }
    }
    __syncthreads();

    // ---- divide by norms + max over q ----
    if (tid < P25) {
        const float snp = sn[tid];
        float m = -INFINITY;
#pragma unroll
        for (int q = 0; q < P25; q++) {
            float den = fmaxf(snp * qn[q], 1e-8f);
            m = fmaxf(m, simbuf[tid * P25 + q] / den);
        }
        out[bs * P25 + tid] = m;
    }
}

extern "C" void kernel_launch(void* const* d_in, const int* in_sizes, int n_in,
                              void* d_out, int out_size)
{
    const float* s_in = (const float*)d_in[0];
    const float* q_in = (const float*)d_in[1];
    float* out = (float*)d_out;

    static bool attr_set = false;
    if (!attr_set) {
        cudaFuncSetAttribute(cosine_kernel,
                             cudaFuncAttributeMaxDynamicSharedMemorySize,
                             COS_SMEM_FLOATS * (int)sizeof(float));
        attr_set = true;
    }

    pool_kernel<<<8000, POOL_THREADS>>>(s_in, q_in, out);
    cosine_kernel<<<BSN, COS_THREADS, COS_SMEM_FLOATS * sizeof(float)>>>(
        out, out + META_TOTAL);
}

// round 8
// speedup vs baseline: 1.4347x; 1.0975x over previous
#include <cuda_runtime.h>
#include <cstdint>
#include <math.h>

#define BSN   100
#define CCH   640
#define W_IN  19
#define IMG   (W_IN * W_IN)           // 361
#define NW    5
#define P25   25
#define META_PER_BS (2 * CCH * P25)   // 32000
#define META_TOTAL  (BSN * META_PER_BS)

// Transposed pooled data: [bs][2][p][c]  (c contiguous)
__device__ float scratch_g[(size_t)BSN * 2 * P25 * CCH];   // 12.8 MB

// ===========================================================================
// Kernel 1: adaptive avg pool 19x19 -> 5x5, cp.async pipelined.
// 2000 blocks x 64 images, 4 chunks of 16 images, double-buffered smem.
// Writes meta (native [ch][p]) AND scratch_g (transposed [p][c]).
// ===========================================================================
#define IMGS_CHUNK 16
#define CHUNK_FLOATS (IMGS_CHUNK * IMG)    // 5776
#define CHUNK_N4 (CHUNK_FLOATS / 4)        // 1444
#define POOL_THREADS 128
#define POOL_FULL 11                       // 11*128=1408, rem 36
#define N_CHUNKS 4
#define POOL_SMEM_FLOATS (2 * CHUNK_FLOATS + IMGS_CHUNK * W_IN * NW) // 13072

__device__ __forceinline__ void cp_async16(unsigned int saddr, const void* gptr) {
    asm volatile("cp.async.cg.shared.global [%0], [%1], 16;\n"
                 :: "r"(saddr), "l"(gptr));
}
__device__ __forceinline__ void cp_commit() {
    asm volatile("cp.async.commit_group;\n");
}
template<int N>
__device__ __forceinline__ void cp_wait() {
    asm volatile("cp.async.wait_group %0;\n" :: "n"(N));
}
__device__ __forceinline__ unsigned int s2u(const void* p) {
    return (unsigned int)__cvta_generic_to_shared(p);
}

__global__ __launch_bounds__(POOL_THREADS, 4) void pool_kernel(
    const float* __restrict__ s_in,
    const float* __restrict__ q_in,
    float* __restrict__ out)
{
    extern __shared__ float psm[];
    float* __restrict__ buf0 = psm;                       // [5776]
    float* __restrict__ buf1 = psm + CHUNK_FLOATS;        // [5776]
    float* __restrict__ sA   = psm + 2 * CHUNK_FLOATS;    // [16*19*5]

    const int blk = blockIdx.x;                // 0..1999
    const int tid = threadIdx.x;
    const int sel = (blk >= 1000) ? 1 : 0;
    const int lblk = blk - sel * 1000;

    const float* __restrict__ gsrc =
        (sel ? q_in : s_in) + (size_t)lblk * (64 * IMG);

    const int img0 = lblk * 64;
    const int bs = img0 / CCH;
    const int c0 = img0 - bs * CCH;            // 64 | 640 => same bs all chunks
    float* __restrict__ meta_base =
        out + (size_t)bs * META_PER_BS + (size_t)(sel * CCH + c0) * P25;
    float* __restrict__ scr_base =
        scratch_g + ((size_t)(bs * 2 + sel) * P25) * CCH;

    // ---- prefetch chunk 0 ----
    {
        const float4* g = (const float4*)(gsrc);
        unsigned int s = s2u(buf0);
#pragma unroll
        for (int k = 0; k < POOL_FULL; k++)
            cp_async16(s + (tid + k * POOL_THREADS) * 16,
                       g + tid + k * POOL_THREADS);
        if (tid < CHUNK_N4 - POOL_FULL * POOL_THREADS)
            cp_async16(s + (POOL_FULL * POOL_THREADS + tid) * 16,
                       g + POOL_FULL * POOL_THREADS + tid);
        cp_commit();
    }

#pragma unroll
    for (int ck = 0; ck < N_CHUNKS; ck++) {
        // prefetch next chunk into the other buffer
        if (ck + 1 < N_CHUNKS) {
            const float4* g = (const float4*)(gsrc + (ck + 1) * CHUNK_FLOATS);
            unsigned int s = s2u(((ck + 1) & 1) ? buf1 : buf0);
#pragma unroll
            for (int k = 0; k < POOL_FULL; k++)
                cp_async16(s + (tid + k * POOL_THREADS) * 16,
                           g + tid + k * POOL_THREADS);
            if (tid < CHUNK_N4 - POOL_FULL * POOL_THREADS)
                cp_async16(s + (POOL_FULL * POOL_THREADS + tid) * 16,
                           g + POOL_FULL * POOL_THREADS + tid);
            cp_commit();
            cp_wait<1>();
        } else {
            cp_wait<0>();
        }
        __syncthreads();   // buffer ck ready; prev chunk's stage B finished

        const float* __restrict__ cbuf = (ck & 1) ? buf1 : buf0;

        // ---- stage A: column-bin rows. 304 tasks ----
#pragma unroll
        for (int base = 0; base < IMGS_CHUNK * W_IN; base += POOL_THREADS) {
            const int idx = base + tid;
            if (idx < IMGS_CHUNK * W_IN) {
                const float* __restrict__ row = cbuf + idx * W_IN;
                float r[W_IN];
#pragma unroll
                for (int w = 0; w < W_IN; w++) r[w] = row[w];
                const int BS_[NW] = {0, 3, 7, 11, 15};
                const int BE_[NW] = {4, 8, 12, 16, 19};
#pragma unroll
                for (int j = 0; j < NW; j++) {
                    float v = 0.0f;
#pragma unroll
                    for (int w = BS_[j]; w < BE_[j]; w++) v += r[w];
                    sA[idx * NW + j] = v;
                }
            }
        }
        __syncthreads();

        // ---- stage B: row-bin + scale; write meta + scratch ----
        const int cc0 = c0 + ck * IMGS_CHUNK;
        float* __restrict__ mdst = meta_base + (size_t)ck * IMGS_CHUNK * P25;
#pragma unroll
        for (int base = 0; base < IMGS_CHUNK * P25; base += POOL_THREADS) {
            const int idx = base + tid;
            if (idx < IMGS_CHUNK * P25) {
                const int img = idx / P25;
                const int o = idx - img * P25;
                const int i = o / NW;
                const int j = o - i * NW;
                const int rs = (19 * i) / 5;
                const int leni = (19 * i + 23) / 5 - rs;
                const int lenj = (19 * j + 23) / 5 - (19 * j) / 5;
                const float* __restrict__ a = sA + (img * W_IN + rs) * NW + j;
                float v = a[0] + a[1 * NW] + a[2 * NW] + a[3 * NW];
                if (leni == 5) v += a[4 * NW];
                const float invi = (leni == 4) ? 0.25f : 0.2f;
                const float invj = (lenj == 4) ? 0.25f : 0.2f;
                v = v * invi * invj;
                mdst[idx] = v;                          // meta  [ch][p]
                scr_base[(size_t)o * CCH + cc0 + img] = v;  // scratch [p][c]
            }
        }
        // no sync here: top-of-loop sync covers sA/buf reuse
    }
}

// ===========================================================================
// Kernel 2: all-pairs cosine similarity + max over query positions.
// 200 blocks: bs = blk/2; half 0 -> p-groups {0,5,10} (15 warps),
// half 1 -> p-groups {15,20} (10 warps). No staging: dot rows read by
// LDG.128 straight from scratch_g (L1/L2-resident working set).
// ===========================================================================
#define COS_THREADS 480

__device__ __forceinline__ void fma_x2(unsigned long long& acc,
                                       unsigned long long a,
                                       unsigned long long b)
{
    asm("fma.rn.f32x2 %0, %1, %2, %0;" : "+l"(acc) : "l"(a), "l"(b));
}

__global__ __launch_bounds__(COS_THREADS) void cosine_kernel(
    float* __restrict__ out)
{
    __shared__ float sn[P25];
    __shared__ float qn[P25];
    __shared__ float simbuf[P25 * P25];

    const int blk = blockIdx.x;
    const int bs = blk >> 1;
    const int half = blk & 1;
    const int tid = threadIdx.x;

    const float* __restrict__ sbase =
        scratch_g + (size_t)(bs * 2 + 0) * P25 * CCH;
    const float* __restrict__ qbase =
        scratch_g + (size_t)(bs * 2 + 1) * P25 * CCH;

    // ---- norms: WARP-UNIFORM. nid = tid>>3 in [0,60); nids >= 50 do a
    // dummy row-0 pass (so every lane of every warp reaches the shuffles)
    // and skip the store. ----
    {
        const int nid = tid >> 3;
        const int sub = tid & 7;
        const bool valid = (nid < 2 * P25);
        const int p = valid ? ((nid >= P25) ? (nid - P25) : nid) : 0;
        const float* __restrict__ f =
            (valid && nid >= P25 ? qbase : sbase) + (size_t)p * CCH;
        float v = 0.0f;
#pragma unroll
        for (int c4 = sub; c4 < CCH / 4; c4 += 8) {
            float4 x = ((const float4*)f)[c4];
            v += x.x * x.x + x.y * x.y + x.z * x.z + x.w * x.w;
        }
        v += __shfl_xor_sync(0xffffffffu, v, 4);
        v += __shfl_xor_sync(0xffffffffu, v, 2);
        v += __shfl_xor_sync(0xffffffffu, v, 1);
        if (valid && sub == 0) {
            if (nid >= P25) qn[p] = sqrtf(v);
            else            sn[p] = sqrtf(v);
        }
    }

    // ---- dots: warp = 5x5 (p,q) tile, LDG.128 lanes over c ----
    // (branch is uniform per warp: w is warp index)
    {
        const int w = tid >> 5;
        const int lane = tid & 31;
        const int ntiles = half ? 10 : 15;
        if (w < ntiles) {
            const int pg = (half ? 15 : 0) + (w / NW) * NW;
            const int qg = (w % NW) * NW;

            unsigned long long acc[NW][NW];
#pragma unroll
            for (int i = 0; i < NW; i++)
#pragma unroll
                for (int j = 0; j < NW; j++) acc[i][j] = 0ull;

#pragma unroll
            for (int k = 0; k < CCH / 128; k++) {   // 5 iters
                const int c = k * 128 + lane * 4;
                longlong2 sv[NW];
#pragma unroll
                for (int i = 0; i < NW; i++)
                    sv[i] = *(const longlong2*)(sbase + (size_t)(pg + i) * CCH + c);
#pragma unroll
                for (int j = 0; j < NW; j++) {
                    const longlong2 qv =
                        *(const longlong2*)(qbase + (size_t)(qg + j) * CCH + c);
#pragma unroll
                    for (int i = 0; i < NW; i++) {
                        fma_x2(acc[i][j], (unsigned long long)sv[i].x,
                                          (unsigned long long)qv.x);
                        fma_x2(acc[i][j], (unsigned long long)sv[i].y,
                                          (unsigned long long)qv.y);
                    }
                }
            }

            float accs[NW][NW];
#pragma unroll
            for (int i = 0; i < NW; i++)
#pragma unroll
                for (int j = 0; j < NW; j++) {
                    unsigned int lo = (unsigned int)(acc[i][j] & 0xffffffffull);
                    unsigned int hi = (unsigned int)(acc[i][j] >> 32);
                    accs[i][j] = __uint_as_float(lo) + __uint_as_float(hi);
                }
#pragma unroll
            for (int off = 16; off; off >>= 1)
#pragma unroll
                for (int i = 0; i < NW; i++)
#pragma unroll
                    for (int j = 0; j < NW; j++)
                        accs[i][j] += __shfl_down_sync(0xffffffffu, accs[i][j], off);

            if (lane == 0) {
#pragma unroll
                for (int i = 0; i < NW; i++)
#pragma unroll
                    for (int j = 0; j < NW; j++)
                        simbuf[(pg + i) * P25 + (qg + j)] = accs[i][j];
            }
        }
    }
    __syncthreads();

    // ---- divide by norms + max over q; write this half's p rows ----
    const int nrows = half ? 10 : 15;
    if (tid < nrows) {
        const int p = (half ? 15 : 0) + tid;
        const float snp = sn[p];
        float m = -INFINITY;
#pragma unroll
        for (int q = 0; q < P25; q++) {
            float den = fmaxf(snp * qn[q], 1e-8f);
            m = fmaxf(m, simbuf[p * P25 + q] / den);
        }
        out[bs * P25 + p] = m;
    }
}

extern "C" void kernel_launch(void* const* d_in, const int* in_sizes, int n_in,
                              void* d_out, int out_size)
{
    const float* s_in = (const float*)d_in[0];
    const float* q_in = (const float*)d_in[1];
    float* out = (float*)d_out;

    static bool attr_set = false;
    if (!attr_set) {
        cudaFuncSetAttribute(pool_kernel,
                             cudaFuncAttributeMaxDynamicSharedMemorySize,
                             POOL_SMEM_FLOATS * (int)sizeof(float));
        attr_set = true;
    }

    pool_kernel<<<2000, POOL_THREADS, POOL_SMEM_FLOATS * sizeof(float)>>>(
        s_in, q_in, out);
    cosine_kernel<<<2 * BSN, COS_THREADS>>>(out + META_TOTAL);
}